// round 5
// baseline (speedup 1.0000x reference)
#include <cuda_runtime.h>

// RNN_26895085207932 : Elman RNN, SEQ=2048, B=4096, IN=1, H=32 + Linear(32->1)
// R3: issue-bound fix — 4 independent fma2 accumulator chains (was 2, capping a
// warp at 0.5 instr/cyc during matvec) + MUFU.TANH (saves ~10 instr/step).

typedef unsigned long long ull;

static constexpr int SEQ = 2048;
static constexpr int B   = 4096;
static constexpr int H   = 32;

__device__ __forceinline__ ull pack2(float lo, float hi) {
    ull r; asm("mov.b64 %0, {%1, %2};" : "=l"(r) : "f"(lo), "f"(hi)); return r;
}
__device__ __forceinline__ void unpack2(ull v, float& lo, float& hi) {
    asm("mov.b64 {%0, %1}, %2;" : "=f"(lo), "=f"(hi) : "l"(v));
}
__device__ __forceinline__ ull fma2(ull a, ull b, ull c) {
    ull d; asm("fma.rn.f32x2 %0, %1, %2, %3;" : "=l"(d) : "l"(a), "l"(b), "l"(c)); return d;
}
__device__ __forceinline__ ull add2(ull a, ull b) {
    ull d; asm("add.rn.f32x2 %0, %1, %2;" : "=l"(d) : "l"(a), "l"(b)); return d;
}
__device__ __forceinline__ ull mul2(ull a, ull b) {
    ull d; asm("mul.rn.f32x2 %0, %1, %2;" : "=l"(d) : "l"(a), "l"(b)); return d;
}
// MUFU.TANH : 1 instr, abs err ~2^-10.8 — recurrence is contractive (rho~0.58),
// expected propagated error ~1e-4 << 1e-3 threshold.
__device__ __forceinline__ float tanh_fast(float z) {
    float r; asm("tanh.approx.f32 %0, %1;" : "=f"(r) : "f"(z)); return r;
}

__global__ void __launch_bounds__(32, 14)
rnn_kernel(const float* __restrict__ x,      // (SEQ, B, 1)
           const float* __restrict__ hidden, // (1, B, H)
           const float* __restrict__ Wih,    // (H, 1)
           const float* __restrict__ bih,    // (H)
           const float* __restrict__ Whh,    // (H, H)
           const float* __restrict__ bhh,    // (H)
           const float* __restrict__ Wfc,    // (1, H)
           const float* __restrict__ bfc,    // (1)
           float* __restrict__ out)          // (SEQ, B, 1)
{
    __shared__ __align__(16) float2 hbuf[2][H];     // double-buffered hidden state
    __shared__ __align__(16) float2 phist[32][34];  // wfc[j]*h ring (padded rows)

    const int j  = threadIdx.x;   // hidden unit owned by this lane
    const int bx = blockIdx.x;    // batch pair
    const int b0 = bx * 2;

    ull w2[H];
#pragma unroll
    for (int k = 0; k < H; k++) {
        float w = Whh[j * H + k];
        w2[k] = pack2(w, w);
    }
    const float wih  = Wih[j];
    const float bias = bih[j] + bhh[j];
    const ull wih2   = pack2(wih, wih);
    const ull bias2  = pack2(bias, bias);
    const float wfc  = Wfc[j];
    const ull wfc2   = pack2(wfc, wfc);
    const float bfc0 = bfc[0];

    hbuf[0][j] = make_float2(hidden[(size_t)b0 * H + j], hidden[(size_t)(b0 + 1) * H + j]);
    __syncwarp();

    const float2* xg = reinterpret_cast<const float2*>(x) + bx;   // step s at xg[s*(B/2)]
    float2* og       = reinterpret_cast<float2*>(out) + bx;

    float2 xpipe[4];
#pragma unroll
    for (int i = 0; i < 4; i++) xpipe[i] = xg[(size_t)i * (B / 2)];

    for (int base = 0; base < SEQ; base += 32) {
#pragma unroll 2
        for (int q = 0; q < 8; q++) {
#pragma unroll
            for (int u = 0; u < 4; u++) {
                const int st = base + q * 4 + u;
                const int p  = st & 1;
                float2 xs = xpipe[u];
                if (st + 4 < SEQ) xpipe[u] = xg[(size_t)(st + 4) * (B / 2)];

                // acc = x*W_ih + (b_ih + b_hh), packed over 2 batches
                ull acc0 = fma2(pack2(xs.x, xs.y), wih2, bias2);
                ull acc1 = 0, acc2 = 0, acc3 = 0;  // 4 independent chains

                // h_{t-1} @ W_hh^T row j : 16 broadcast LDS.128, 4 fma2 chains
                const ulonglong2* hb = reinterpret_cast<const ulonglong2*>(hbuf[p]);
#pragma unroll
                for (int g = 0; g < 8; g++) {
                    ulonglong2 ha = hb[2 * g];
                    ulonglong2 hc = hb[2 * g + 1];
                    acc0 = fma2(ha.x, w2[4 * g],     acc0);
                    acc1 = fma2(ha.y, w2[4 * g + 1], acc1);
                    acc2 = fma2(hc.x, w2[4 * g + 2], acc2);
                    acc3 = fma2(hc.y, w2[4 * g + 3], acc3);
                }
                ull acc = add2(add2(acc0, acc1), add2(acc2, acc3));

                float zA, zB;
                unpack2(acc, zA, zB);
                const float hA = tanh_fast(zA);
                const float hB = tanh_fast(zB);
                const ull h2 = pack2(hA, hB);

                hbuf[p ^ 1][j] = make_float2(hA, hB);
                ull ph = mul2(h2, wfc2);
                float pA, pB;
                unpack2(ph, pA, pB);
                phist[st & 31][j] = make_float2(pA, pB);
                __syncwarp();
            }
        }

        // Transposed output reduction (amortized over 32 steps)
        {
            const ulonglong2* pr = reinterpret_cast<const ulonglong2*>(&phist[j][0]);
            ull s0 = 0, s1 = 0, s2 = 0, s3 = 0;
#pragma unroll
            for (int g = 0; g < 8; g++) {
                ulonglong2 a = pr[2 * g];
                ulonglong2 b = pr[2 * g + 1];
                s0 = add2(s0, a.x); s1 = add2(s1, a.y);
                s2 = add2(s2, b.x); s3 = add2(s3, b.y);
            }
            ull sv = add2(add2(s0, s1), add2(s2, s3));
            float oA, oB;
            unpack2(sv, oA, oB);
            og[(size_t)(base + j) * (B / 2)] = make_float2(oA + bfc0, oB + bfc0);
            __syncwarp();
        }
    }
}

extern "C" void kernel_launch(void* const* d_in, const int* in_sizes, int n_in,
                              void* d_out, int out_size) {
    const float* x      = (const float*)d_in[0];
    const float* hidden = (const float*)d_in[1];
    const float* Wih    = (const float*)d_in[2];
    const float* bih    = (const float*)d_in[3];
    const float* Whh    = (const float*)d_in[4];
    const float* bhh    = (const float*)d_in[5];
    const float* Wfc    = (const float*)d_in[6];
    const float* bfc    = (const float*)d_in[7];
    (void)in_sizes; (void)n_in; (void)out_size;

    rnn_kernel<<<B / 2, 32>>>(x, hidden, Wih, bih, Whh, bhh, Wfc, bfc, (float*)d_out);
}

// round 6
// speedup vs baseline: 1.1552x; 1.1552x over previous
#include <cuda_runtime.h>

// RNN_26895085207932 : Elman RNN, SEQ=2048, B=4096, IN=1, H=32 + Linear(32->1)
// R5: split-k matvec. Evidence: L1tex wavefront pipe ~78% = binding. Each lane
// now reads only HALF of h (8 LDS.128, was 16) and computes half-dots for two
// units; one packed shfl_xor(16) completes both dots across the lane pair.
// MIO wavefronts/step ~35 -> ~20.

typedef unsigned long long ull;

static constexpr int SEQ = 2048;
static constexpr int B   = 4096;
static constexpr int H   = 32;

__device__ __forceinline__ ull pack2(float lo, float hi) {
    ull r; asm("mov.b64 %0, {%1, %2};" : "=l"(r) : "f"(lo), "f"(hi)); return r;
}
__device__ __forceinline__ void unpack2(ull v, float& lo, float& hi) {
    asm("mov.b64 {%0, %1}, %2;" : "=f"(lo), "=f"(hi) : "l"(v));
}
__device__ __forceinline__ ull fma2(ull a, ull b, ull c) {
    ull d; asm("fma.rn.f32x2 %0, %1, %2, %3;" : "=l"(d) : "l"(a), "l"(b), "l"(c)); return d;
}
__device__ __forceinline__ ull add2(ull a, ull b) {
    ull d; asm("add.rn.f32x2 %0, %1, %2;" : "=l"(d) : "l"(a), "l"(b)); return d;
}
__device__ __forceinline__ ull mul2(ull a, ull b) {
    ull d; asm("mul.rn.f32x2 %0, %1, %2;" : "=l"(d) : "l"(a), "l"(b)); return d;
}
__device__ __forceinline__ ull shfl_xor2(ull v, int d) {
    unsigned lo = (unsigned)v, hi = (unsigned)(v >> 32);
    lo = __shfl_xor_sync(0xffffffffu, lo, d);
    hi = __shfl_xor_sync(0xffffffffu, hi, d);
    return ((ull)hi << 32) | (ull)lo;
}
// MUFU.TANH: abs err ~2^-10.8, contractive recurrence -> measured rel_err ~6e-6.
__device__ __forceinline__ float tanh_fast(float z) {
    float r; asm("tanh.approx.f32 %0, %1;" : "=f"(r) : "f"(z)); return r;
}

__global__ void __launch_bounds__(32, 14)
rnn_kernel(const float* __restrict__ x,      // (SEQ, B, 1)
           const float* __restrict__ hidden, // (1, B, H)
           const float* __restrict__ Wih,    // (H, 1)
           const float* __restrict__ bih,    // (H)
           const float* __restrict__ Whh,    // (H, H)
           const float* __restrict__ bhh,    // (H)
           const float* __restrict__ Wfc,    // (1, H)
           const float* __restrict__ bfc,    // (1)
           float* __restrict__ out)          // (SEQ, B, 1)
{
    __shared__ __align__(16) float2 hbuf[2][H];     // double-buffered hidden state
    __shared__ __align__(16) float2 phist[32][34];  // wfc[u]*h ring (padded rows)

    const int j    = threadIdx.x;
    const int r    = j & 15;        // lane-pair index
    const int half = j >> 4;        // which k-half this lane reads
    const int myu  = 2 * r + half;  // hidden unit this lane finally owns
    const int u0   = 2 * r;         // unit of partial p0
    const int u1   = 2 * r + 1;     // unit of partial p1
    const int kofs = 16 * half;     // k-range start

    const int bx = blockIdx.x;      // batch pair
    const int b0 = bx * 2;

    // Weights for the two units over this lane's k-half (32 packed regs).
    ull wa[16], wb[16];
#pragma unroll
    for (int k = 0; k < 16; k++) {
        float a = Whh[u0 * H + kofs + k];
        float b = Whh[u1 * H + kofs + k];
        wa[k] = pack2(a, a);
        wb[k] = pack2(b, b);
    }
    const float wih  = Wih[myu];
    const float bias = bih[myu] + bhh[myu];
    const ull wih2   = pack2(wih, wih);
    const ull bias2  = pack2(bias, bias);
    const float wfc  = Wfc[myu];
    const ull wfc2   = pack2(wfc, wfc);
    const float bfc0 = bfc[0];

    hbuf[0][j] = make_float2(hidden[(size_t)b0 * H + j], hidden[(size_t)(b0 + 1) * H + j]);
    __syncwarp();

    const float2* xg = reinterpret_cast<const float2*>(x) + bx;   // step s at xg[s*(B/2)]
    float2* og       = reinterpret_cast<float2*>(out) + bx;

    float2 xpipe[4];
#pragma unroll
    for (int i = 0; i < 4; i++) xpipe[i] = xg[(size_t)i * (B / 2)];

    for (int base = 0; base < SEQ; base += 32) {
#pragma unroll 2
        for (int q = 0; q < 8; q++) {
#pragma unroll
            for (int u = 0; u < 4; u++) {
                const int st = base + q * 4 + u;
                const int p  = st & 1;
                float2 xs = xpipe[u];
                if (st + 4 < SEQ) xpipe[u] = xg[(size_t)(st + 4) * (B / 2)];

                // Half-dots for units u0,u1 over k in [kofs, kofs+16):
                // 8 broadcast LDS.128 (this lane's half only), 4 fma2 chains x8.
                const ulonglong2* hb =
                    reinterpret_cast<const ulonglong2*>(&hbuf[p][kofs]);
                ull p0a = 0, p0b = 0, p1a = 0, p1b = 0;
#pragma unroll
                for (int g = 0; g < 4; g++) {
                    ulonglong2 hv = hb[2 * g];
                    ulonglong2 hw = hb[2 * g + 1];
                    p0a = fma2(hv.x, wa[4 * g],     p0a);
                    p1a = fma2(hv.x, wb[4 * g],     p1a);
                    p0b = fma2(hv.y, wa[4 * g + 1], p0b);
                    p1b = fma2(hv.y, wb[4 * g + 1], p1b);
                    p0a = fma2(hw.x, wa[4 * g + 2], p0a);
                    p1a = fma2(hw.x, wb[4 * g + 2], p1a);
                    p0b = fma2(hw.y, wa[4 * g + 3], p0b);
                    p1b = fma2(hw.y, wb[4 * g + 3], p1b);
                }
                ull p0 = add2(p0a, p0b);   // partial for unit u0 (this k-half)
                ull p1 = add2(p1a, p1b);   // partial for unit u1 (this k-half)

                // Pair exchange: keep my unit's partial, send partner's.
                ull keep = half ? p1 : p0;
                ull send = half ? p0 : p1;
                ull recv = shfl_xor2(send, 16);

                // z = full dot + x*W_ih + biases (all for unit myu)
                ull xb = fma2(pack2(xs.x, xs.y), wih2, bias2);
                ull z  = add2(add2(keep, recv), xb);

                float zA, zB;
                unpack2(z, zA, zB);
                const float hA = tanh_fast(zA);
                const float hB = tanh_fast(zB);
                const ull h2 = pack2(hA, hB);

                hbuf[p ^ 1][myu] = make_float2(hA, hB);
                ull ph = mul2(h2, wfc2);
                float pA, pB;
                unpack2(ph, pA, pB);
                phist[st & 31][myu] = make_float2(pA, pB);
                __syncwarp();
            }
        }

        // Transposed output reduction (amortized over 32 steps):
        // lane j sums row j (all 32 units' partials of timestep base+j).
        {
            const ulonglong2* pr = reinterpret_cast<const ulonglong2*>(&phist[j][0]);
            ull s0 = 0, s1 = 0, s2 = 0, s3 = 0;
#pragma unroll
            for (int g = 0; g < 8; g++) {
                ulonglong2 a = pr[2 * g];
                ulonglong2 b = pr[2 * g + 1];
                s0 = add2(s0, a.x); s1 = add2(s1, a.y);
                s2 = add2(s2, b.x); s3 = add2(s3, b.y);
            }
            ull sv = add2(add2(s0, s1), add2(s2, s3));
            float oA, oB;
            unpack2(sv, oA, oB);
            og[(size_t)(base + j) * (B / 2)] = make_float2(oA + bfc0, oB + bfc0);
            __syncwarp();
        }
    }
}

extern "C" void kernel_launch(void* const* d_in, const int* in_sizes, int n_in,
                              void* d_out, int out_size) {
    const float* x      = (const float*)d_in[0];
    const float* hidden = (const float*)d_in[1];
    const float* Wih    = (const float*)d_in[2];
    const float* bih    = (const float*)d_in[3];
    const float* Whh    = (const float*)d_in[4];
    const float* bhh    = (const float*)d_in[5];
    const float* Wfc    = (const float*)d_in[6];
    const float* bfc    = (const float*)d_in[7];
    (void)in_sizes; (void)n_in; (void)out_size;

    rnn_kernel<<<B / 2, 32>>>(x, hidden, Wih, bih, Whh, bhh, Wfc, bfc, (float*)d_out);
}

// round 7
// speedup vs baseline: 1.1555x; 1.0003x over previous
#include <cuda_runtime.h>

// RNN_26895085207932 : Elman RNN, SEQ=2048, B=4096, IN=1, H=32 + Linear(32->1)
// R6: instruction/latency diet. Pre-swapped split-k weights (no keep/send sels),
// no syncwarps (convergent warp + full-mask shfl each step gives ordering),
// single h buffer, packed 64-bit STS, pointer-increment addressing.

typedef unsigned long long ull;

static constexpr int SEQ = 2048;
static constexpr int B   = 4096;
static constexpr int H   = 32;

__device__ __forceinline__ ull pack2(float lo, float hi) {
    ull r; asm("mov.b64 %0, {%1, %2};" : "=l"(r) : "f"(lo), "f"(hi)); return r;
}
__device__ __forceinline__ void unpack2(ull v, float& lo, float& hi) {
    asm("mov.b64 {%0, %1}, %2;" : "=f"(lo), "=f"(hi) : "l"(v));
}
__device__ __forceinline__ ull fma2(ull a, ull b, ull c) {
    ull d; asm("fma.rn.f32x2 %0, %1, %2, %3;" : "=l"(d) : "l"(a), "l"(b), "l"(c)); return d;
}
__device__ __forceinline__ ull add2(ull a, ull b) {
    ull d; asm("add.rn.f32x2 %0, %1, %2;" : "=l"(d) : "l"(a), "l"(b)); return d;
}
__device__ __forceinline__ ull mul2(ull a, ull b) {
    ull d; asm("mul.rn.f32x2 %0, %1, %2;" : "=l"(d) : "l"(a), "l"(b)); return d;
}
__device__ __forceinline__ ull shfl_xor2(ull v, int d) {
    unsigned lo = (unsigned)v, hi = (unsigned)(v >> 32);
    lo = __shfl_xor_sync(0xffffffffu, lo, d);
    hi = __shfl_xor_sync(0xffffffffu, hi, d);
    return ((ull)hi << 32) | (ull)lo;
}
__device__ __forceinline__ float tanh_fast(float z) {
    float r; asm("tanh.approx.f32 %0, %1;" : "=f"(r) : "f"(z)); return r;
}
__device__ __forceinline__ void sts64(ull v, const void* p) {
    asm volatile("st.shared.b64 [%0], %1;"
                 :: "l"(__cvta_generic_to_shared(p)), "l"(v) : "memory");
}

__global__ void __launch_bounds__(32, 14)
rnn_kernel(const float* __restrict__ x,      // (SEQ, B, 1)
           const float* __restrict__ hidden, // (1, B, H)
           const float* __restrict__ Wih,    // (H, 1)
           const float* __restrict__ bih,    // (H)
           const float* __restrict__ Whh,    // (H, H)
           const float* __restrict__ bhh,    // (H)
           const float* __restrict__ Wfc,    // (1, H)
           const float* __restrict__ bfc,    // (1)
           float* __restrict__ out)          // (SEQ, B, 1)
{
    __shared__ __align__(16) float2 hbuf[H];        // single-buffered hidden state
    __shared__ __align__(16) float2 phist[32][34];  // wfc*h ring (padded rows)

    const int j    = threadIdx.x;
    const int r    = j & 15;        // lane-pair index
    const int half = j >> 4;        // k-half this lane reads
    const int myu  = 2 * r + half;  // unit this lane owns
    const int ou   = 2 * r + (1 - half);  // partner lane's unit
    const int kofs = 16 * half;

    const int bx = blockIdx.x;      // batch pair
    const int b0 = bx * 2;

    // Pre-swapped weights: chain A (wa) = MY unit's row over my k-half (kept),
    // chain B (wb) = partner's unit row over my k-half (sent via shfl).
    ull wa[16], wb[16];
#pragma unroll
    for (int k = 0; k < 16; k++) {
        float a = Whh[myu * H + kofs + k];
        float b = Whh[ou  * H + kofs + k];
        wa[k] = pack2(a, a);
        wb[k] = pack2(b, b);
    }
    const float wih  = Wih[myu];
    const float bias = bih[myu] + bhh[myu];
    const ull wih2   = pack2(wih, wih);
    const ull bias2  = pack2(bias, bias);
    const float wfc  = Wfc[myu];
    const ull wfc2   = pack2(wfc, wfc);
    const float bfc0 = bfc[0];

    hbuf[j] = make_float2(hidden[(size_t)b0 * H + j], hidden[(size_t)(b0 + 1) * H + j]);
    __syncwarp();  // one-time init ordering

    const float2* xg = reinterpret_cast<const float2*>(x) + bx;   // step stride B/2
    float2* og       = reinterpret_cast<float2*>(out) + bx;

    const ulonglong2* hb = reinterpret_cast<const ulonglong2*>(&hbuf[kofs]);
    float2* hw = &hbuf[myu];

    float2 xpipe[4];
#pragma unroll
    for (int i = 0; i < 4; i++) xpipe[i] = xg[(size_t)i * (B / 2)];
    const float2* xnext = xg + 4 * (size_t)(B / 2);

    for (int base = 0; base < SEQ; base += 32) {
#pragma unroll 1
        for (int q = 0; q < 8; q++) {
            const int s4 = base + q * 4;
#pragma unroll
            for (int u = 0; u < 4; u++) {
                const int st = s4 + u;
                float2 xs = xpipe[u];
                if (st + 4 < SEQ) xpipe[u] = xnext[(size_t)st * (B / 2)];

                // x*W_ih + (b_ih + b_hh) — off the critical path
                ull xb = fma2(pack2(xs.x, xs.y), wih2, bias2);

                // Half-dots: 8 broadcast LDS.128, 4 independent fma2 chains.
                ull p0a = 0, p0b = 0, p1a = 0, p1b = 0;
#pragma unroll
                for (int g = 0; g < 4; g++) {
                    ulonglong2 hv = hb[2 * g];
                    ulonglong2 hw2 = hb[2 * g + 1];
                    p0a = fma2(hv.x,  wa[4 * g],     p0a);
                    p1a = fma2(hv.x,  wb[4 * g],     p1a);
                    p0b = fma2(hv.y,  wa[4 * g + 1], p0b);
                    p1b = fma2(hv.y,  wb[4 * g + 1], p1b);
                    p0a = fma2(hw2.x, wa[4 * g + 2], p0a);
                    p1a = fma2(hw2.x, wb[4 * g + 2], p1a);
                    p0b = fma2(hw2.y, wa[4 * g + 3], p0b);
                    p1b = fma2(hw2.y, wb[4 * g + 3], p1b);
                }
                ull keep = add2(p0a, p0b);            // my unit, my k-half
                ull send = add2(p1a, p1b);            // partner's unit, my k-half
                ull recv = shfl_xor2(send, 16);       // my unit, other k-half

                ull z = add2(add2(keep, recv), xb);

                float zA, zB;
                unpack2(z, zA, zB);
                const float hA = tanh_fast(zA);
                const float hB = tanh_fast(zB);
                const ull h2 = pack2(hA, hB);

                // Program-order smem deps within a convergent warp: all lanes'
                // LDS above retire before these STS issue; next step's LDS
                // follows in program order. Full-mask shfl re-converges each step.
                sts64(h2, hw);
                sts64(mul2(h2, wfc2), &phist[st & 31][myu]);
            }
        }

        // Transposed output reduction: lane j sums row j (timestep base+j).
        {
            const ulonglong2* pr = reinterpret_cast<const ulonglong2*>(&phist[j][0]);
            ull s0 = 0, s1 = 0, s2 = 0, s3 = 0;
#pragma unroll
            for (int g = 0; g < 8; g++) {
                ulonglong2 a = pr[2 * g];
                ulonglong2 b = pr[2 * g + 1];
                s0 = add2(s0, a.x); s1 = add2(s1, a.y);
                s2 = add2(s2, b.x); s3 = add2(s3, b.y);
            }
            ull sv = add2(add2(s0, s1), add2(s2, s3));
            float oA, oB;
            unpack2(sv, oA, oB);
            og[(size_t)(base + j) * (B / 2)] = make_float2(oA + bfc0, oB + bfc0);
        }
    }
}

extern "C" void kernel_launch(void* const* d_in, const int* in_sizes, int n_in,
                              void* d_out, int out_size) {
    const float* x      = (const float*)d_in[0];
    const float* hidden = (const float*)d_in[1];
    const float* Wih    = (const float*)d_in[2];
    const float* bih    = (const float*)d_in[3];
    const float* Whh    = (const float*)d_in[4];
    const float* bhh    = (const float*)d_in[5];
    const float* Wfc    = (const float*)d_in[6];
    const float* bfc    = (const float*)d_in[7];
    (void)in_sizes; (void)n_in; (void)out_size;

    rnn_kernel<<<B / 2, 32>>>(x, hidden, Wih, bih, Whh, bhh, Wfc, bfc, (float*)d_out);
}

// round 8
// speedup vs baseline: 1.1590x; 1.0030x over previous
#include <cuda_runtime.h>

// RNN_26895085207932 : Elman RNN, SEQ=2048, B=4096, IN=1, H=32 + Linear(32->1)
// R7: bank-conflict fix. The split-k matvec LDS.128s have TWO distinct
// addresses per warp (halves 256B apart == same 4-bank group -> 2-way
// conflict, 2 phases each). Skew the upper h half by +16B (2 float2 pad) so
// the paired reads hit disjoint bank groups -> 1 phase per LDS.128.

typedef unsigned long long ull;

static constexpr int SEQ = 2048;
static constexpr int B   = 4096;
static constexpr int H   = 32;

__device__ __forceinline__ ull pack2(float lo, float hi) {
    ull r; asm("mov.b64 %0, {%1, %2};" : "=l"(r) : "f"(lo), "f"(hi)); return r;
}
__device__ __forceinline__ void unpack2(ull v, float& lo, float& hi) {
    asm("mov.b64 {%0, %1}, %2;" : "=f"(lo), "=f"(hi) : "l"(v));
}
__device__ __forceinline__ ull fma2(ull a, ull b, ull c) {
    ull d; asm("fma.rn.f32x2 %0, %1, %2, %3;" : "=l"(d) : "l"(a), "l"(b), "l"(c)); return d;
}
__device__ __forceinline__ ull add2(ull a, ull b) {
    ull d; asm("add.rn.f32x2 %0, %1, %2;" : "=l"(d) : "l"(a), "l"(b)); return d;
}
__device__ __forceinline__ ull mul2(ull a, ull b) {
    ull d; asm("mul.rn.f32x2 %0, %1, %2;" : "=l"(d) : "l"(a), "l"(b)); return d;
}
__device__ __forceinline__ ull shfl_xor2(ull v, int d) {
    unsigned lo = (unsigned)v, hi = (unsigned)(v >> 32);
    lo = __shfl_xor_sync(0xffffffffu, lo, d);
    hi = __shfl_xor_sync(0xffffffffu, hi, d);
    return ((ull)hi << 32) | (ull)lo;
}
__device__ __forceinline__ float tanh_fast(float z) {
    float r; asm("tanh.approx.f32 %0, %1;" : "=f"(r) : "f"(z)); return r;
}
__device__ __forceinline__ void sts64(ull v, const void* p) {
    asm volatile("st.shared.b64 [%0], %1;"
                 :: "l"(__cvta_generic_to_shared(p)), "l"(v) : "memory");
}

__global__ void __launch_bounds__(32, 14)
rnn_kernel(const float* __restrict__ x,      // (SEQ, B, 1)
           const float* __restrict__ hidden, // (1, B, H)
           const float* __restrict__ Wih,    // (H, 1)
           const float* __restrict__ bih,    // (H)
           const float* __restrict__ Whh,    // (H, H)
           const float* __restrict__ bhh,    // (H)
           const float* __restrict__ Wfc,    // (1, H)
           const float* __restrict__ bfc,    // (1)
           float* __restrict__ out)          // (SEQ, B, 1)
{
    // hbuf layout: units 0..15 at [0..15], 16B pad at [16..17], units 16..31
    // at [18..33]. The +272B separation => paired LDS addresses land in
    // disjoint 4-bank groups (272/4 = 68 == +4 banks mod 32).
    __shared__ __align__(16) float2 hbuf[H + 2];
    __shared__ __align__(16) float2 phist[32][34];  // wfc*h ring (padded rows)

    const int j    = threadIdx.x;
    const int r    = j & 15;        // lane-pair index
    const int half = j >> 4;        // k-half this lane reads
    const int myu  = 2 * r + half;  // unit this lane owns
    const int ou   = 2 * r + (1 - half);  // partner lane's unit
    const int kofs = 16 * half;

    const int bx = blockIdx.x;      // batch pair
    const int b0 = bx * 2;

    // Pre-swapped weights: wa = MY unit's row over my k-half (kept),
    // wb = partner's unit row over my k-half (sent via shfl).
    ull wa[16], wb[16];
#pragma unroll
    for (int k = 0; k < 16; k++) {
        float a = Whh[myu * H + kofs + k];
        float b = Whh[ou  * H + kofs + k];
        wa[k] = pack2(a, a);
        wb[k] = pack2(b, b);
    }
    const float wih  = Wih[myu];
    const float bias = bih[myu] + bhh[myu];
    const ull wih2   = pack2(wih, wih);
    const ull bias2  = pack2(bias, bias);
    const float wfc  = Wfc[myu];
    const ull wfc2   = pack2(wfc, wfc);
    const float bfc0 = bfc[0];

    // skewed index: u<16 -> u ; u>=16 -> u+2
    hbuf[j + ((j >> 4) << 1)] =
        make_float2(hidden[(size_t)b0 * H + j], hidden[(size_t)(b0 + 1) * H + j]);
    __syncwarp();  // one-time init ordering

    const float2* xg = reinterpret_cast<const float2*>(x) + bx;   // step stride B/2
    float2* og       = reinterpret_cast<float2*>(out) + bx;

    // this lane's k-half, skewed: half0 -> &hbuf[0], half1 -> &hbuf[18]
    const ulonglong2* hb = reinterpret_cast<const ulonglong2*>(&hbuf[kofs + 2 * half]);
    float2* hw = &hbuf[myu + ((myu >> 4) << 1)];

    float2 xpipe[4];
#pragma unroll
    for (int i = 0; i < 4; i++) xpipe[i] = xg[(size_t)i * (B / 2)];
    const float2* xnext = xg + 4 * (size_t)(B / 2);

    for (int base = 0; base < SEQ; base += 32) {
#pragma unroll 1
        for (int q = 0; q < 8; q++) {
            const int s4 = base + q * 4;
#pragma unroll
            for (int u = 0; u < 4; u++) {
                const int st = s4 + u;
                float2 xs = xpipe[u];
                if (st + 4 < SEQ) xpipe[u] = xnext[(size_t)st * (B / 2)];

                // x*W_ih + (b_ih + b_hh) — off the critical path
                ull xb = fma2(pack2(xs.x, xs.y), wih2, bias2);

                // Half-dots: 8 conflict-free broadcast LDS.128, 4 fma2 chains.
                ull p0a = 0, p0b = 0, p1a = 0, p1b = 0;
#pragma unroll
                for (int g = 0; g < 4; g++) {
                    ulonglong2 hv  = hb[2 * g];
                    ulonglong2 hw2 = hb[2 * g + 1];
                    p0a = fma2(hv.x,  wa[4 * g],     p0a);
                    p1a = fma2(hv.x,  wb[4 * g],     p1a);
                    p0b = fma2(hv.y,  wa[4 * g + 1], p0b);
                    p1b = fma2(hv.y,  wb[4 * g + 1], p1b);
                    p0a = fma2(hw2.x, wa[4 * g + 2], p0a);
                    p1a = fma2(hw2.x, wb[4 * g + 2], p1a);
                    p0b = fma2(hw2.y, wa[4 * g + 3], p0b);
                    p1b = fma2(hw2.y, wb[4 * g + 3], p1b);
                }
                ull keep = add2(p0a, p0b);            // my unit, my k-half
                ull send = add2(p1a, p1b);            // partner's unit, my k-half
                ull recv = shfl_xor2(send, 16);       // my unit, other k-half

                ull z = add2(add2(keep, recv), xb);

                float zA, zB;
                unpack2(z, zA, zB);
                const float hA = tanh_fast(zA);
                const float hB = tanh_fast(zB);
                const ull h2 = pack2(hA, hB);

                // Same-warp program-order smem deps; full-mask shfl each step
                // keeps the warp converged.
                sts64(h2, hw);
                sts64(mul2(h2, wfc2), &phist[st & 31][myu]);
            }
        }

        // Transposed output reduction: lane j sums row j (timestep base+j).
        {
            const ulonglong2* pr = reinterpret_cast<const ulonglong2*>(&phist[j][0]);
            ull s0 = 0, s1 = 0, s2 = 0, s3 = 0;
#pragma unroll
            for (int g = 0; g < 8; g++) {
                ulonglong2 a = pr[2 * g];
                ulonglong2 b = pr[2 * g + 1];
                s0 = add2(s0, a.x); s1 = add2(s1, a.y);
                s2 = add2(s2, b.x); s3 = add2(s3, b.y);
            }
            ull sv = add2(add2(s0, s1), add2(s2, s3));
            float oA, oB;
            unpack2(sv, oA, oB);
            og[(size_t)(base + j) * (B / 2)] = make_float2(oA + bfc0, oB + bfc0);
        }
    }
}

extern "C" void kernel_launch(void* const* d_in, const int* in_sizes, int n_in,
                              void* d_out, int out_size) {
    const float* x      = (const float*)d_in[0];
    const float* hidden = (const float*)d_in[1];
    const float* Wih    = (const float*)d_in[2];
    const float* bih    = (const float*)d_in[3];
    const float* Whh    = (const float*)d_in[4];
    const float* bhh    = (const float*)d_in[5];
    const float* Wfc    = (const float*)d_in[6];
    const float* bfc    = (const float*)d_in[7];
    (void)in_sizes; (void)n_in; (void)out_size;

    rnn_kernel<<<B / 2, 32>>>(x, hidden, Wih, bih, Whh, bhh, Wfc, bfc, (float*)d_out);
}

// round 9
// speedup vs baseline: 1.1610x; 1.0017x over previous
#include <cuda_runtime.h>

// RNN_26895085207932 : Elman RNN, SEQ=2048, B=4096, IN=1, H=32 + Linear(32->1)
// R7: bank-conflict fix. The split-k matvec LDS.128s have TWO distinct
// addresses per warp (halves 256B apart == same 4-bank group -> 2-way
// conflict, 2 phases each). Skew the upper h half by +16B (2 float2 pad) so
// the paired reads hit disjoint bank groups -> 1 phase per LDS.128.

typedef unsigned long long ull;

static constexpr int SEQ = 2048;
static constexpr int B   = 4096;
static constexpr int H   = 32;

__device__ __forceinline__ ull pack2(float lo, float hi) {
    ull r; asm("mov.b64 %0, {%1, %2};" : "=l"(r) : "f"(lo), "f"(hi)); return r;
}
__device__ __forceinline__ void unpack2(ull v, float& lo, float& hi) {
    asm("mov.b64 {%0, %1}, %2;" : "=f"(lo), "=f"(hi) : "l"(v));
}
__device__ __forceinline__ ull fma2(ull a, ull b, ull c) {
    ull d; asm("fma.rn.f32x2 %0, %1, %2, %3;" : "=l"(d) : "l"(a), "l"(b), "l"(c)); return d;
}
__device__ __forceinline__ ull add2(ull a, ull b) {
    ull d; asm("add.rn.f32x2 %0, %1, %2;" : "=l"(d) : "l"(a), "l"(b)); return d;
}
__device__ __forceinline__ ull mul2(ull a, ull b) {
    ull d; asm("mul.rn.f32x2 %0, %1, %2;" : "=l"(d) : "l"(a), "l"(b)); return d;
}
__device__ __forceinline__ ull shfl_xor2(ull v, int d) {
    unsigned lo = (unsigned)v, hi = (unsigned)(v >> 32);
    lo = __shfl_xor_sync(0xffffffffu, lo, d);
    hi = __shfl_xor_sync(0xffffffffu, hi, d);
    return ((ull)hi << 32) | (ull)lo;
}
__device__ __forceinline__ float tanh_fast(float z) {
    float r; asm("tanh.approx.f32 %0, %1;" : "=f"(r) : "f"(z)); return r;
}
__device__ __forceinline__ void sts64(ull v, const void* p) {
    asm volatile("st.shared.b64 [%0], %1;"
                 :: "l"(__cvta_generic_to_shared(p)), "l"(v) : "memory");
}

__global__ void __launch_bounds__(32, 14)
rnn_kernel(const float* __restrict__ x,      // (SEQ, B, 1)
           const float* __restrict__ hidden, // (1, B, H)
           const float* __restrict__ Wih,    // (H, 1)
           const float* __restrict__ bih,    // (H)
           const float* __restrict__ Whh,    // (H, H)
           const float* __restrict__ bhh,    // (H)
           const float* __restrict__ Wfc,    // (1, H)
           const float* __restrict__ bfc,    // (1)
           float* __restrict__ out)          // (SEQ, B, 1)
{
    // hbuf layout: units 0..15 at [0..15], 16B pad at [16..17], units 16..31
    // at [18..33]. The +272B separation => paired LDS addresses land in
    // disjoint 4-bank groups (272/4 = 68 == +4 banks mod 32).
    __shared__ __align__(16) float2 hbuf[H + 2];
    __shared__ __align__(16) float2 phist[32][34];  // wfc*h ring (padded rows)

    const int j    = threadIdx.x;
    const int r    = j & 15;        // lane-pair index
    const int half = j >> 4;        // k-half this lane reads
    const int myu  = 2 * r + half;  // unit this lane owns
    const int ou   = 2 * r + (1 - half);  // partner lane's unit
    const int kofs = 16 * half;

    const int bx = blockIdx.x;      // batch pair
    const int b0 = bx * 2;

    // Pre-swapped weights: wa = MY unit's row over my k-half (kept),
    // wb = partner's unit row over my k-half (sent via shfl).
    ull wa[16], wb[16];
#pragma unroll
    for (int k = 0; k < 16; k++) {
        float a = Whh[myu * H + kofs + k];
        float b = Whh[ou  * H + kofs + k];
        wa[k] = pack2(a, a);
        wb[k] = pack2(b, b);
    }
    const float wih  = Wih[myu];
    const float bias = bih[myu] + bhh[myu];
    const ull wih2   = pack2(wih, wih);
    const ull bias2  = pack2(bias, bias);
    const float wfc  = Wfc[myu];
    const ull wfc2   = pack2(wfc, wfc);
    const float bfc0 = bfc[0];

    // skewed index: u<16 -> u ; u>=16 -> u+2
    hbuf[j + ((j >> 4) << 1)] =
        make_float2(hidden[(size_t)b0 * H + j], hidden[(size_t)(b0 + 1) * H + j]);
    __syncwarp();  // one-time init ordering

    const float2* xg = reinterpret_cast<const float2*>(x) + bx;   // step stride B/2
    float2* og       = reinterpret_cast<float2*>(out) + bx;

    // this lane's k-half, skewed: half0 -> &hbuf[0], half1 -> &hbuf[18]
    const ulonglong2* hb = reinterpret_cast<const ulonglong2*>(&hbuf[kofs + 2 * half]);
    float2* hw = &hbuf[myu + ((myu >> 4) << 1)];

    float2 xpipe[4];
#pragma unroll
    for (int i = 0; i < 4; i++) xpipe[i] = xg[(size_t)i * (B / 2)];
    const float2* xnext = xg + 4 * (size_t)(B / 2);

    for (int base = 0; base < SEQ; base += 32) {
#pragma unroll 1
        for (int q = 0; q < 8; q++) {
            const int s4 = base + q * 4;
#pragma unroll
            for (int u = 0; u < 4; u++) {
                const int st = s4 + u;
                float2 xs = xpipe[u];
                if (st + 4 < SEQ) xpipe[u] = xnext[(size_t)st * (B / 2)];

                // x*W_ih + (b_ih + b_hh) — off the critical path
                ull xb = fma2(pack2(xs.x, xs.y), wih2, bias2);

                // Half-dots: 8 conflict-free broadcast LDS.128, 4 fma2 chains.
                ull p0a = 0, p0b = 0, p1a = 0, p1b = 0;
#pragma unroll
                for (int g = 0; g < 4; g++) {
                    ulonglong2 hv  = hb[2 * g];
                    ulonglong2 hw2 = hb[2 * g + 1];
                    p0a = fma2(hv.x,  wa[4 * g],     p0a);
                    p1a = fma2(hv.x,  wb[4 * g],     p1a);
                    p0b = fma2(hv.y,  wa[4 * g + 1], p0b);
                    p1b = fma2(hv.y,  wb[4 * g + 1], p1b);
                    p0a = fma2(hw2.x, wa[4 * g + 2], p0a);
                    p1a = fma2(hw2.x, wb[4 * g + 2], p1a);
                    p0b = fma2(hw2.y, wa[4 * g + 3], p0b);
                    p1b = fma2(hw2.y, wb[4 * g + 3], p1b);
                }
                ull keep = add2(p0a, p0b);            // my unit, my k-half
                ull send = add2(p1a, p1b);            // partner's unit, my k-half
                ull recv = shfl_xor2(send, 16);       // my unit, other k-half

                ull z = add2(add2(keep, recv), xb);

                float zA, zB;
                unpack2(z, zA, zB);
                const float hA = tanh_fast(zA);
                const float hB = tanh_fast(zB);
                const ull h2 = pack2(hA, hB);

                // Same-warp program-order smem deps; full-mask shfl each step
                // keeps the warp converged.
                sts64(h2, hw);
                sts64(mul2(h2, wfc2), &phist[st & 31][myu]);
            }
        }

        // Transposed output reduction: lane j sums row j (timestep base+j).
        {
            const ulonglong2* pr = reinterpret_cast<const ulonglong2*>(&phist[j][0]);
            ull s0 = 0, s1 = 0, s2 = 0, s3 = 0;
#pragma unroll
            for (int g = 0; g < 8; g++) {
                ulonglong2 a = pr[2 * g];
                ulonglong2 b = pr[2 * g + 1];
                s0 = add2(s0, a.x); s1 = add2(s1, a.y);
                s2 = add2(s2, b.x); s3 = add2(s3, b.y);
            }
            ull sv = add2(add2(s0, s1), add2(s2, s3));
            float oA, oB;
            unpack2(sv, oA, oB);
            og[(size_t)(base + j) * (B / 2)] = make_float2(oA + bfc0, oB + bfc0);
        }
    }
}

extern "C" void kernel_launch(void* const* d_in, const int* in_sizes, int n_in,
                              void* d_out, int out_size) {
    const float* x      = (const float*)d_in[0];
    const float* hidden = (const float*)d_in[1];
    const float* Wih    = (const float*)d_in[2];
    const float* bih    = (const float*)d_in[3];
    const float* Whh    = (const float*)d_in[4];
    const float* bhh    = (const float*)d_in[5];
    const float* Wfc    = (const float*)d_in[6];
    const float* bfc    = (const float*)d_in[7];
    (void)in_sizes; (void)n_in; (void)out_size;

    rnn_kernel<<<B / 2, 32>>>(x, hidden, Wih, bih, Whh, bhh, Wfc, bfc, (float*)d_out);
}

// round 10
// speedup vs baseline: 1.1918x; 1.0266x over previous
#include <cuda_runtime.h>

// RNN_26895085207932 : Elman RNN, SEQ=2048, B=4096, IN=1, H=32 + Linear(32->1)
// R9: split-k-4 matvec. Evidence: only MIO-op cuts have ever helped; LDS.128
// costs 2 wavefronts each, so halving matvec LDS (8->4) cuts the dominant
// wavefront load even after +2 packed shuffles for the extra butterfly round.
// Quartet {j, j^8, j^16, j^24}: lane computes 4 units' partials over its
// k-quarter; xor8 then xor16 rounds complete all dots. Quarter bases skewed
// +16B so the 4 distinct LDS addresses hit disjoint bank groups.

typedef unsigned long long ull;

static constexpr int SEQ = 2048;
static constexpr int B   = 4096;
static constexpr int H   = 32;

__device__ __forceinline__ ull pack2(float lo, float hi) {
    ull r; asm("mov.b64 %0, {%1, %2};" : "=l"(r) : "f"(lo), "f"(hi)); return r;
}
__device__ __forceinline__ void unpack2(ull v, float& lo, float& hi) {
    asm("mov.b64 {%0, %1}, %2;" : "=f"(lo), "=f"(hi) : "l"(v));
}
__device__ __forceinline__ ull fma2(ull a, ull b, ull c) {
    ull d; asm("fma.rn.f32x2 %0, %1, %2, %3;" : "=l"(d) : "l"(a), "l"(b), "l"(c)); return d;
}
__device__ __forceinline__ ull add2(ull a, ull b) {
    ull d; asm("add.rn.f32x2 %0, %1, %2;" : "=l"(d) : "l"(a), "l"(b)); return d;
}
__device__ __forceinline__ ull mul2(ull a, ull b) {
    ull d; asm("mul.rn.f32x2 %0, %1, %2;" : "=l"(d) : "l"(a), "l"(b)); return d;
}
__device__ __forceinline__ ull shfl_xor2(ull v, int d) {
    unsigned lo = (unsigned)v, hi = (unsigned)(v >> 32);
    lo = __shfl_xor_sync(0xffffffffu, lo, d);
    hi = __shfl_xor_sync(0xffffffffu, hi, d);
    return ((ull)hi << 32) | (ull)lo;
}
__device__ __forceinline__ float tanh_fast(float z) {
    float r; asm("tanh.approx.f32 %0, %1;" : "=f"(r) : "f"(z)); return r;
}
__device__ __forceinline__ void sts64(ull v, const void* p) {
    asm volatile("st.shared.b64 [%0], %1;"
                 :: "l"(__cvta_generic_to_shared(p)), "l"(v) : "memory");
}

// Skewed hbuf index: unit u lives at u + 2*(u/8)  (16B pad between k-quarters).
__device__ __forceinline__ int skew(int u) { return u + ((u >> 3) << 1); }

__global__ void __launch_bounds__(32, 14)
rnn_kernel(const float* __restrict__ x,      // (SEQ, B, 1)
           const float* __restrict__ hidden, // (1, B, H)
           const float* __restrict__ Wih,    // (H, 1)
           const float* __restrict__ bih,    // (H)
           const float* __restrict__ Whh,    // (H, H)
           const float* __restrict__ bhh,    // (H)
           const float* __restrict__ Wfc,    // (1, H)
           const float* __restrict__ bfc,    // (1)
           float* __restrict__ out)          // (SEQ, B, 1)
{
    __shared__ __align__(16) float2 hbuf[H + 6];    // skewed: quarters at 0/10/20/30
    __shared__ __align__(16) float2 phist[32][34];  // wfc*h ring (padded rows)

    const int j = threadIdx.x;
    const int q = j >> 3;          // k-quarter this lane reads (0..3)
    const int g = j & 7;           // quartet group (0..7)
    const int myu = 4 * g + q;           // unit this lane finally owns
    const int ub  = 4 * g + (q ^ 1);     // unit of lane j^8
    const int uc  = 4 * g + (q ^ 2);     // unit of lane j^16
    const int ud  = 4 * g + (q ^ 3);     // unit of lane j^24
    const int kofs = 8 * q;              // k-range start (8 wide)

    const int bx = blockIdx.x;     // batch pair
    const int b0 = bx * 2;

    // Weights: rows of the 4 quartet units over MY k-quarter, packed.
    ull wa[8], wb[8], wc[8], wd[8];
#pragma unroll
    for (int k = 0; k < 8; k++) {
        float a = Whh[myu * H + kofs + k];
        float b = Whh[ub  * H + kofs + k];
        float c = Whh[uc  * H + kofs + k];
        float d = Whh[ud  * H + kofs + k];
        wa[k] = pack2(a, a);
        wb[k] = pack2(b, b);
        wc[k] = pack2(c, c);
        wd[k] = pack2(d, d);
    }
    const float wih  = Wih[myu];
    const float bias = bih[myu] + bhh[myu];
    const ull wih2   = pack2(wih, wih);
    const ull bias2  = pack2(bias, bias);
    const float wfc  = Wfc[myu];
    const ull wfc2   = pack2(wfc, wfc);
    const float bfc0 = bfc[0];

    hbuf[skew(myu)] =
        make_float2(hidden[(size_t)b0 * H + myu], hidden[(size_t)(b0 + 1) * H + myu]);
    __syncwarp();  // one-time init ordering

    const float2* xg = reinterpret_cast<const float2*>(x) + bx;   // step stride B/2
    float2* og       = reinterpret_cast<float2*>(out) + bx;

    // My k-quarter: 8 units = 4x 16B reads, base at skewed quarter start (q*10).
    const ulonglong2* hq = reinterpret_cast<const ulonglong2*>(&hbuf[10 * q]);
    float2* hw = &hbuf[skew(myu)];

    float2 xpipe[4];
#pragma unroll
    for (int i = 0; i < 4; i++) xpipe[i] = xg[(size_t)i * (B / 2)];
    const float2* xnext = xg + 4 * (size_t)(B / 2);

    for (int base = 0; base < SEQ; base += 32) {
#pragma unroll 2
        for (int qq = 0; qq < 8; qq++) {
            const int s4 = base + qq * 4;
#pragma unroll
            for (int u = 0; u < 4; u++) {
                const int st = s4 + u;
                float2 xs = xpipe[u];
                if (st + 4 < SEQ) xpipe[u] = xnext[(size_t)st * (B / 2)];

                // 4 independent fma2 chains, one per quartet unit; chain A
                // starts from x*W_ih + biases (saves a merge add).
                ull pA = fma2(pack2(xs.x, xs.y), wih2, bias2);
                ull pB = 0, pC = 0, pD = 0;
#pragma unroll
                for (int g2 = 0; g2 < 2; g2++) {
                    ulonglong2 h0 = hq[2 * g2];
                    ulonglong2 h1 = hq[2 * g2 + 1];
                    pA = fma2(h0.x, wa[4 * g2],     pA);
                    pB = fma2(h0.x, wb[4 * g2],     pB);
                    pC = fma2(h0.x, wc[4 * g2],     pC);
                    pD = fma2(h0.x, wd[4 * g2],     pD);
                    pA = fma2(h0.y, wa[4 * g2 + 1], pA);
                    pB = fma2(h0.y, wb[4 * g2 + 1], pB);
                    pC = fma2(h0.y, wc[4 * g2 + 1], pC);
                    pD = fma2(h0.y, wd[4 * g2 + 1], pD);
                    pA = fma2(h1.x, wa[4 * g2 + 2], pA);
                    pB = fma2(h1.x, wb[4 * g2 + 2], pB);
                    pC = fma2(h1.x, wc[4 * g2 + 2], pC);
                    pD = fma2(h1.x, wd[4 * g2 + 2], pD);
                    pA = fma2(h1.y, wa[4 * g2 + 3], pA);
                    pB = fma2(h1.y, wb[4 * g2 + 3], pB);
                    pC = fma2(h1.y, wc[4 * g2 + 3], pC);
                    pD = fma2(h1.y, wd[4 * g2 + 3], pD);
                }

                // Butterfly round 1 (xor 8): partner has quarter q^1.
                // recvB = my unit over q^1 ; recvD = unit uc over q^1.
                ull recvB = shfl_xor2(pB, 8);
                ull recvD = shfl_xor2(pD, 8);
                ull sA = add2(pA, recvB);   // unit myu over {q, q^1} (+x+bias)
                ull sC = add2(pC, recvD);   // unit uc  over {q, q^1}

                // Round 2 (xor 16): partner's sC = my unit over {q^2, q^3}.
                ull recv2 = shfl_xor2(sC, 16);
                ull z = add2(sA, recv2);

                float zA, zB;
                unpack2(z, zA, zB);
                const float hA = tanh_fast(zA);
                const float hB = tanh_fast(zB);
                const ull h2 = pack2(hA, hB);

                // Same-warp program-order smem deps; full-mask shfls keep the
                // warp converged each step.
                sts64(h2, hw);
                sts64(mul2(h2, wfc2), &phist[st & 31][myu]);
            }
        }

        // Transposed output reduction: lane j sums row j (timestep base+j).
        {
            const ulonglong2* pr = reinterpret_cast<const ulonglong2*>(&phist[j][0]);
            ull s0 = 0, s1 = 0, s2 = 0, s3 = 0;
#pragma unroll
            for (int g2 = 0; g2 < 8; g2++) {
                ulonglong2 a = pr[2 * g2];
                ulonglong2 b = pr[2 * g2 + 1];
                s0 = add2(s0, a.x); s1 = add2(s1, a.y);
                s2 = add2(s2, b.x); s3 = add2(s3, b.y);
            }
            ull sv = add2(add2(s0, s1), add2(s2, s3));
            float oA, oB;
            unpack2(sv, oA, oB);
            og[(size_t)(base + j) * (B / 2)] = make_float2(oA + bfc0, oB + bfc0);
        }
    }
}

extern "C" void kernel_launch(void* const* d_in, const int* in_sizes, int n_in,
                              void* d_out, int out_size) {
    const float* x      = (const float*)d_in[0];
    const float* hidden = (const float*)d_in[1];
    const float* Wih    = (const float*)d_in[2];
    const float* bih    = (const float*)d_in[3];
    const float* Whh    = (const float*)d_in[4];
    const float* bhh    = (const float*)d_in[5];
    const float* Wfc    = (const float*)d_in[6];
    const float* bfc    = (const float*)d_in[7];
    (void)in_sizes; (void)n_in; (void)out_size;

    rnn_kernel<<<B / 2, 32>>>(x, hidden, Wih, bih, Whh, bhh, Wfc, bfc, (float*)d_out);
}